// round 12
// baseline (speedup 1.0000x reference)
#include <cuda_runtime.h>
#include <cuda_bf16.h>
#include <cstdint>
#include <math.h>

#define NP    400000
#define NKER  27
#define CIN   64
#define COUT  38
#define TILE  256
#define NT256 1563               // ceil(400000/256); last tile has 128 valid rows

// smem: A rows (256) + W rows (40), padded to 144B row stride (conflict-free)
#define ROWPAD   144
#define A_PLANE  (TILE * ROWPAD)            // 36864
#define W_PLANE  (40 * ROWPAD)              // 5760
#define SM_W     (2 * A_PLANE)              // 73728
#define SMEM_DYN (SM_W + 2 * W_PLANE)       // 85248  (needs opt-in; 2 CTAs/SM)

// ---- device-global scratch (zero-initialized at module load; padding row NP
//      and pad columns are NEVER written, so they stay zero) ----
__device__ __align__(256) __nv_bfloat16 g_fhi[(NP + 1) * 64];
__device__ __align__(256) __nv_bfloat16 g_flo[(NP + 1) * 64];
__device__ __align__(256) __nv_bfloat16 g_hhi[(NP + 1) * 48];   // cols 38..47 stay 0
__device__ __align__(256) __nv_bfloat16 g_hlo[(NP + 1) * 48];
__device__ __align__(256) __nv_bfloat16 g_w1hi[NKER * 40 * 64]; // [k][cout(40)][cin]
__device__ __align__(256) __nv_bfloat16 g_w1lo[NKER * 40 * 64];
__device__ __align__(256) __nv_bfloat16 g_w2hi[NKER * 40 * 48];
__device__ __align__(256) __nv_bfloat16 g_w2lo[NKER * 40 * 48];

// ---------------- helpers ----------------
__device__ __forceinline__ uint32_t smem_u32(const void* p) {
    uint32_t a;
    asm("{ .reg .u64 t; cvta.to.shared.u64 t, %1; cvt.u32.u64 %0, t; }" : "=r"(a) : "l"(p));
    return a;
}
__device__ __forceinline__ void ldsm_x4(uint32_t* r, uint32_t addr) {
    asm volatile("ldmatrix.sync.aligned.m8n8.x4.shared.b16 {%0,%1,%2,%3}, [%4];"
                 : "=r"(r[0]), "=r"(r[1]), "=r"(r[2]), "=r"(r[3]) : "r"(addr));
}
__device__ __forceinline__ void cp_async16(uint32_t dst, const void* src) {
    asm volatile("cp.async.cg.shared.global [%0], [%1], 16;"
                 :: "r"(dst), "l"(src) : "memory");
}
__device__ __forceinline__ void cp_commit_wait0() {
    asm volatile("cp.async.commit_group;" ::: "memory");
    asm volatile("cp.async.wait_group 0;" ::: "memory");
}
__device__ __forceinline__ void mma_bf16(float* d, const uint32_t* a, const uint32_t* b) {
    asm volatile(
        "mma.sync.aligned.m16n8k16.row.col.f32.bf16.bf16.f32 "
        "{%0,%1,%2,%3}, {%4,%5,%6,%7}, {%8,%9}, {%0,%1,%2,%3};"
        : "+f"(d[0]), "+f"(d[1]), "+f"(d[2]), "+f"(d[3])
        : "r"(a[0]), "r"(a[1]), "r"(a[2]), "r"(a[3]), "r"(b[0]), "r"(b[1]));
}

// ---------------- prep kernels ----------------
__global__ void k_prep_f(const float* __restrict__ f, long n) {
    long i = (long)blockIdx.x * blockDim.x + threadIdx.x;
    if (i >= n) return;
    float x = f[i];
    __nv_bfloat16 h = __float2bfloat16(x);
    __nv_bfloat16 l = __float2bfloat16(x - __bfloat162float(h));
    g_fhi[i] = h; g_flo[i] = l;
}
__global__ void k_prep_w1(const float* __restrict__ w) {
    int t = blockIdx.x * blockDim.x + threadIdx.x;
    if (t >= NKER * CIN * COUT) return;
    int k  = t / (CIN * COUT);
    int r  = t - k * CIN * COUT;
    int ci = r / COUT;
    int co = r - ci * COUT;
    float x = w[t];
    __nv_bfloat16 h = __float2bfloat16(x);
    __nv_bfloat16 l = __float2bfloat16(x - __bfloat162float(h));
    int di = (k * 40 + co) * 64 + ci;
    g_w1hi[di] = h; g_w1lo[di] = l;
}
__global__ void k_prep_w2(const float* __restrict__ w) {
    int t = blockIdx.x * blockDim.x + threadIdx.x;
    if (t >= NKER * COUT * COUT) return;
    int k  = t / (COUT * COUT);
    int r  = t - k * COUT * COUT;
    int ci = r / COUT;
    int co = r - ci * COUT;
    float x = w[t];
    __nv_bfloat16 h = __float2bfloat16(x);
    __nv_bfloat16 l = __float2bfloat16(x - __bfloat162float(h));
    int di = (k * 40 + co) * 48 + ci;
    g_w2hi[di] = h; g_w2lo[di] = l;
}

// ---------------- main layer kernel ----------------
// out[i] = sum_k W[k]^T A[nbr[k,i]] via HMMA, bf16 2-term split (3 mma passes).
// ROWB16: 16B chunks per feature row (8 -> 64 cols, 6 -> 48 cols); KSTEPS = k16 chunks.
template<int ROWB16, int KSTEPS, bool IS_L1>
__global__ void __launch_bounds__(256, 2)
layer_kernel(const __nv_bfloat16* __restrict__ Ahi, const __nv_bfloat16* __restrict__ Alo,
             const __nv_bfloat16* __restrict__ Whi, const __nv_bfloat16* __restrict__ Wlo,
             const int* __restrict__ nbr, float* __restrict__ out) {
    extern __shared__ char smem[];
    const uint32_t sbase = smem_u32(smem);
    const int t    = threadIdx.x;
    const int wid  = t >> 5, lane = t & 31;
    const int tile = blockIdx.x;
    const int ROWE = ROWB16 * 8;   // bf16 elems per row in global planes

    float acc[2][5][4];
    #pragma unroll
    for (int m = 0; m < 2; m++)
        #pragma unroll
        for (int n = 0; n < 5; n++)
            #pragma unroll
            for (int j = 0; j < 4; j++) acc[m][n][j] = 0.0f;

    const uint32_t smA_hi = sbase;
    const uint32_t smA_lo = sbase + A_PLANE;
    const uint32_t smW_hi = sbase + SM_W;
    const uint32_t smW_lo = smW_hi + W_PLANE;

    const int p     = tile * TILE + t;          // gather row owned by this thread
    const bool pok  = (p < NP);

    // B ldmatrix.x4 lane base: m0=hi k0-7, m1=hi k8-15, m2=lo k0-7, m3=lo k8-15
    const uint32_t bbase = ((lane & 16) ? smW_lo : smW_hi)
                         + (uint32_t)(lane & 7) * ROWPAD + ((lane >> 3) & 1) * 16;
    // A ldmatrix.x4 lane pieces
    const uint32_t arow  = (uint32_t)(wid * 32 + (lane & 15)) * ROWPAD;
    const uint32_t ahalf = (uint32_t)((lane >> 4) * 16);

    for (int k = 0; k < NKER; k++) {
        __syncthreads();   // previous stage's compute done before overwriting smem
        // ---- gather one feature row per thread via cp.async (hi + lo planes) ----
        {
            int idx = pok ? nbr[(size_t)k * NP + p] : NP;   // NP -> zero row
            const char* sh = (const char*)(Ahi + (size_t)idx * ROWE);
            const char* sl = (const char*)(Alo + (size_t)idx * ROWE);
            const uint32_t dh = smA_hi + (uint32_t)t * ROWPAD;
            #pragma unroll
            for (int j = 0; j < ROWB16; j++) {
                cp_async16(dh + j * 16,           sh + j * 16);
                cp_async16(dh + A_PLANE + j * 16, sl + j * 16);
            }
        }
        // ---- stage W[k] tile (40 rows) via cp.async ----
        {
            const char* wh = (const char*)(Whi + (size_t)k * 40 * ROWE);
            const char* wl = (const char*)(Wlo + (size_t)k * 40 * ROWE);
            #pragma unroll 2
            for (int i = t; i < 40 * ROWB16; i += 256) {
                int n = i / ROWB16, j = i - n * ROWB16;
                uint32_t d = smW_hi + (uint32_t)n * ROWPAD + j * 16;
                cp_async16(d,           wh + (size_t)i * 16);
                cp_async16(d + W_PLANE, wl + (size_t)i * 16);
            }
        }
        cp_commit_wait0();
        __syncthreads();
        // ---- compute ----
        #pragma unroll
        for (int s = 0; s < KSTEPS; s++) {
            uint32_t bh[5][2], bl[5][2];
            #pragma unroll
            for (int nt = 0; nt < 5; nt++) {
                uint32_t r[4];
                ldsm_x4(r, bbase + (uint32_t)(nt * 8) * ROWPAD + s * 32);
                bh[nt][0] = r[0]; bh[nt][1] = r[1];
                bl[nt][0] = r[2]; bl[nt][1] = r[3];
            }
            #pragma unroll
            for (int mt = 0; mt < 2; mt++) {
                uint32_t ah[4], al[4];
                const uint32_t ao = arow + (uint32_t)(mt * 16) * ROWPAD
                                  + s * 32 + ahalf;
                ldsm_x4(ah, smA_hi + ao);
                ldsm_x4(al, smA_lo + ao);
                #pragma unroll
                for (int nt = 0; nt < 5; nt++) {
                    mma_bf16(acc[mt][nt], ah, bh[nt]);   // hi*hi
                    mma_bf16(acc[mt][nt], ah, bl[nt]);   // hi*lo
                    mma_bf16(acc[mt][nt], al, bh[nt]);   // lo*hi
                }
            }
        }
    }

    // ---- epilogue ----
    const int rbase = wid * 32 + (lane >> 2);
    #pragma unroll
    for (int mt = 0; mt < 2; mt++) {
        const int p0 = tile * TILE + rbase + mt * 16;     // rows p0, p0+8
        #pragma unroll
        for (int nt = 0; nt < 5; nt++) {
            const int c = nt * 8 + (lane & 3) * 2;
            if (c >= COUT) continue;                      // cols 38,39 discarded
            #pragma unroll
            for (int h = 0; h < 2; h++) {
                const int pr = p0 + h * 8;
                if (pr >= NP) continue;                   // partial last tile
                float v0 = acc[mt][nt][2 * h + 0];
                float v1 = acc[mt][nt][2 * h + 1];
                if (IS_L1) {
                    float g0 = 0.5f * v0 * (1.0f + erff(v0 * 0.70710678118654752f));
                    float g1 = 0.5f * v1 * (1.0f + erff(v1 * 0.70710678118654752f));
                    __nv_bfloat16 h0 = __float2bfloat16(g0);
                    __nv_bfloat16 h1 = __float2bfloat16(g1);
                    __nv_bfloat16 l0 = __float2bfloat16(g0 - __bfloat162float(h0));
                    __nv_bfloat16 l1 = __float2bfloat16(g1 - __bfloat162float(h1));
                    *(__nv_bfloat162*)(g_hhi + (size_t)pr * 48 + c) = __nv_bfloat162(h0, h1);
                    *(__nv_bfloat162*)(g_hlo + (size_t)pr * 48 + c) = __nv_bfloat162(l0, l1);
                } else {
                    *(float2*)(out + (size_t)pr * COUT + c) = make_float2(v0, v1);
                }
            }
        }
    }
}

// ---------------- launch ----------------
extern "C" void kernel_launch(void* const* d_in, const int* in_sizes, int n_in,
                              void* d_out, int out_size) {
    const float* features = (const float*)d_in[0];   // [400000, 64]  f32
    const int*   nbr      = (const int*)d_in[1];     // [27, 400000]  i32
    const float* W1       = (const float*)d_in[2];   // [27, 64, 38]  f32
    const float* W2       = (const float*)d_in[3];   // [27, 38, 38]  f32
    float* out = (float*)d_out;                      // [400000, 38]  f32

    cudaFuncSetAttribute(layer_kernel<8, 4, true>,
                         cudaFuncAttributeMaxDynamicSharedMemorySize, SMEM_DYN);
    cudaFuncSetAttribute(layer_kernel<6, 3, false>,
                         cudaFuncAttributeMaxDynamicSharedMemorySize, SMEM_DYN);

    __nv_bfloat16 *fhi, *flo, *hhi, *hlo, *w1h, *w1l, *w2h, *w2l;
    cudaGetSymbolAddress((void**)&fhi, g_fhi);
    cudaGetSymbolAddress((void**)&flo, g_flo);
    cudaGetSymbolAddress((void**)&hhi, g_hhi);
    cudaGetSymbolAddress((void**)&hlo, g_hlo);
    cudaGetSymbolAddress((void**)&w1h, g_w1hi);
    cudaGetSymbolAddress((void**)&w1l, g_w1lo);
    cudaGetSymbolAddress((void**)&w2h, g_w2hi);
    cudaGetSymbolAddress((void**)&w2l, g_w2lo);

    long nf = (long)NP * 64;
    k_prep_f <<<(unsigned)((nf + 255) / 256), 256>>>(features, nf);
    k_prep_w1<<<(NKER * CIN  * COUT + 255) / 256, 256>>>(W1);
    k_prep_w2<<<(NKER * COUT * COUT + 255) / 256, 256>>>(W2);

    layer_kernel<8, 4, true ><<<NT256, 256, SMEM_DYN>>>(fhi, flo, w1h, w1l, nbr, nullptr);
    layer_kernel<6, 3, false><<<NT256, 256, SMEM_DYN>>>(hhi, hlo, w2h, w2l, nbr, out);
}

// round 16
// speedup vs baseline: 35.4303x; 35.4303x over previous
#include <cuda_runtime.h>
#include <cuda_bf16.h>
#include <cstdint>
#include <math.h>

#define NP    400000
#define NKER  27
#define CIN   64
#define COUT  38
#define NTILE 3125              // 3125*128 == 400000 exactly

// smem: A rows (128) + W rows (40), all padded to 144B row stride
#define ROWPAD   144
#define A_PLANE  (128 * ROWPAD)          // 18432
#define SM_W     (2 * A_PLANE)           // 36864
#define W_PLANE  (40 * ROWPAD)           // 5760
#define SMEM_DYN (SM_W + 2 * W_PLANE)    // 48384  (<= 48KB default, 4 CTA/SM)

// ---- device-global scratch (zero-initialized at module load; padding row NP
//      and pad columns are NEVER written, so they stay zero) ----
__device__ __align__(256) __nv_bfloat16 g_fhi[(NP + 1) * 64];
__device__ __align__(256) __nv_bfloat16 g_flo[(NP + 1) * 64];
__device__ __align__(256) __nv_bfloat16 g_hhi[(NP + 1) * 48];   // cols 38..47 stay 0
__device__ __align__(256) __nv_bfloat16 g_hlo[(NP + 1) * 48];
__device__ __align__(256) __nv_bfloat16 g_w1hi[NKER * 40 * 64]; // [k][cout(40)][cin]
__device__ __align__(256) __nv_bfloat16 g_w1lo[NKER * 40 * 64];
__device__ __align__(256) __nv_bfloat16 g_w2hi[NKER * 40 * 48];
__device__ __align__(256) __nv_bfloat16 g_w2lo[NKER * 40 * 48];

// ---------------- helpers ----------------
__device__ __forceinline__ uint32_t smem_u32(const void* p) {
    uint32_t a;
    asm("{ .reg .u64 t; cvta.to.shared.u64 t, %1; cvt.u32.u64 %0, t; }" : "=r"(a) : "l"(p));
    return a;
}
__device__ __forceinline__ void ldsm_x4(uint32_t* r, uint32_t addr) {
    asm volatile("ldmatrix.sync.aligned.m8n8.x4.shared.b16 {%0,%1,%2,%3}, [%4];"
                 : "=r"(r[0]), "=r"(r[1]), "=r"(r[2]), "=r"(r[3]) : "r"(addr));
}
__device__ __forceinline__ void mma_bf16(float* d, const uint32_t* a, const uint32_t* b) {
    asm volatile(
        "mma.sync.aligned.m16n8k16.row.col.f32.bf16.bf16.f32 "
        "{%0,%1,%2,%3}, {%4,%5,%6,%7}, {%8,%9}, {%0,%1,%2,%3};"
        : "+f"(d[0]), "+f"(d[1]), "+f"(d[2]), "+f"(d[3])
        : "r"(a[0]), "r"(a[1]), "r"(a[2]), "r"(a[3]), "r"(b[0]), "r"(b[1]));
}

// ---------------- prep kernels ----------------
__global__ void k_prep_f(const float* __restrict__ f, long n) {
    long i = (long)blockIdx.x * blockDim.x + threadIdx.x;
    if (i >= n) return;
    float x = f[i];
    __nv_bfloat16 h = __float2bfloat16(x);
    __nv_bfloat16 l = __float2bfloat16(x - __bfloat162float(h));
    g_fhi[i] = h; g_flo[i] = l;
}
__global__ void k_prep_w1(const float* __restrict__ w) {
    int t = blockIdx.x * blockDim.x + threadIdx.x;
    if (t >= NKER * CIN * COUT) return;
    int k  = t / (CIN * COUT);
    int r  = t - k * CIN * COUT;
    int ci = r / COUT;
    int co = r - ci * COUT;
    float x = w[t];
    __nv_bfloat16 h = __float2bfloat16(x);
    __nv_bfloat16 l = __float2bfloat16(x - __bfloat162float(h));
    int di = (k * 40 + co) * 64 + ci;
    g_w1hi[di] = h; g_w1lo[di] = l;
}
__global__ void k_prep_w2(const float* __restrict__ w) {
    int t = blockIdx.x * blockDim.x + threadIdx.x;
    if (t >= NKER * COUT * COUT) return;
    int k  = t / (COUT * COUT);
    int r  = t - k * COUT * COUT;
    int ci = r / COUT;
    int co = r - ci * COUT;
    float x = w[t];
    __nv_bfloat16 h = __float2bfloat16(x);
    __nv_bfloat16 l = __float2bfloat16(x - __bfloat162float(h));
    int di = (k * 40 + co) * 48 + ci;
    g_w2hi[di] = h; g_w2lo[di] = l;
}

// ---------------- main layer kernel ----------------
// out[i] = sum_k W[k]^T A[nbr[k,i]] via HMMA, bf16 2-term split (3 mma passes).
// ROWB16: 16B chunks per feature row (8 -> 64 cols, 6 -> 48 cols); KSTEPS = k16 chunks.
template<int ROWB16, int KSTEPS, bool IS_L1>
__global__ void __launch_bounds__(128)
layer_kernel(const __nv_bfloat16* __restrict__ Ahi, const __nv_bfloat16* __restrict__ Alo,
             const __nv_bfloat16* __restrict__ Whi, const __nv_bfloat16* __restrict__ Wlo,
             const int* __restrict__ nbr, float* __restrict__ out) {
    extern __shared__ char smem[];
    const uint32_t sbase = smem_u32(smem);
    const int t    = threadIdx.x;
    const int wid  = t >> 5, lane = t & 31;
    const int tile = blockIdx.x;
    const int ROWE = ROWB16 * 8;   // bf16 elems per row in global planes

    float acc[2][5][4];
    #pragma unroll
    for (int m = 0; m < 2; m++)
        #pragma unroll
        for (int n = 0; n < 5; n++)
            #pragma unroll
            for (int j = 0; j < 4; j++) acc[m][n][j] = 0.0f;

    const uint32_t smA_hi = sbase;
    const uint32_t smA_lo = sbase + A_PLANE;
    const uint32_t smW_hi = sbase + SM_W;
    const uint32_t smW_lo = smW_hi + W_PLANE;

    // B ldmatrix.x4 lane base: m0=hi k0-7, m1=hi k8-15, m2=lo k0-7, m3=lo k8-15
    // (bit-identical to the scalar-loaded fragments: verified in R12, same rel_err)
    const uint32_t bbase = ((lane & 16) ? smW_lo : smW_hi)
                         + (uint32_t)(lane & 7) * ROWPAD + ((lane >> 3) & 1) * 16;
    // A ldmatrix.x4 lane pieces
    const uint32_t arow  = (uint32_t)(wid * 32 + (lane & 15)) * ROWPAD;
    const uint32_t ahalf = (uint32_t)((lane >> 4) * 16);

    for (int k = 0; k < NKER; k++) {
        __syncthreads();   // previous compute done before overwriting smem
        // ---- gather one feature row per thread (hi + lo planes, via L1) ----
        {
            int idx = nbr[(size_t)k * NP + tile * 128 + t];   // idx==NP -> zero row
            const uint4* sh = (const uint4*)(Ahi + (size_t)idx * ROWE);
            const uint4* sl = (const uint4*)(Alo + (size_t)idx * ROWE);
            uint4* dh = (uint4*)(smem + (size_t)t * ROWPAD);
            uint4* dl = (uint4*)(smem + A_PLANE + (size_t)t * ROWPAD);
            #pragma unroll
            for (int j = 0; j < ROWB16; j++) { dh[j] = sh[j]; dl[j] = sl[j]; }
        }
        // ---- stage W[k] tile: 40 rows x ROWB16 chunks, hi + lo ----
        {
            const uint4* wh = (const uint4*)(Whi + (size_t)k * 40 * ROWE);
            const uint4* wl = (const uint4*)(Wlo + (size_t)k * 40 * ROWE);
            for (int i = t; i < 40 * ROWB16; i += 128) {
                int n = i / ROWB16, j = i - n * ROWB16;
                ((uint4*)(smem + SM_W + (size_t)n * ROWPAD))[j] = wh[i];
                ((uint4*)(smem + SM_W + W_PLANE + (size_t)n * ROWPAD))[j] = wl[i];
            }
        }
        __syncthreads();
        // ---- compute ----
        #pragma unroll
        for (int s = 0; s < KSTEPS; s++) {
            uint32_t bh[5][2], bl[5][2];
            #pragma unroll
            for (int nt = 0; nt < 5; nt++) {
                uint32_t r[4];
                ldsm_x4(r, bbase + (uint32_t)(nt * 8) * ROWPAD + s * 32);
                bh[nt][0] = r[0]; bh[nt][1] = r[1];
                bl[nt][0] = r[2]; bl[nt][1] = r[3];
            }
            #pragma unroll
            for (int mt = 0; mt < 2; mt++) {
                uint32_t ah[4], al[4];
                const uint32_t ao = arow + (uint32_t)(mt * 16) * ROWPAD + s * 32 + ahalf;
                ldsm_x4(ah, smA_hi + ao);
                ldsm_x4(al, smA_lo + ao);
                #pragma unroll
                for (int nt = 0; nt < 5; nt++) {
                    mma_bf16(acc[mt][nt], ah, bh[nt]);   // hi*hi
                    mma_bf16(acc[mt][nt], ah, bl[nt]);   // hi*lo
                    mma_bf16(acc[mt][nt], al, bh[nt]);   // lo*hi
                }
            }
        }
    }

    // ---- epilogue ----
    // D frag: d0,d1 -> (row r, cols c,c+1); d2,d3 -> (row r+8, cols c,c+1)
    const int rbase = wid * 32 + (lane >> 2);
    #pragma unroll
    for (int mt = 0; mt < 2; mt++) {
        const int p0 = tile * 128 + rbase + mt * 16;     // rows p0, p0+8
        #pragma unroll
        for (int nt = 0; nt < 5; nt++) {
            const int c = nt * 8 + (lane & 3) * 2;
            if (c >= COUT) continue;                     // cols 38,39 discarded
            #pragma unroll
            for (int h = 0; h < 2; h++) {
                const int p = p0 + h * 8;
                float v0 = acc[mt][nt][2 * h + 0];
                float v1 = acc[mt][nt][2 * h + 1];
                if (IS_L1) {
                    float g0 = 0.5f * v0 * (1.0f + erff(v0 * 0.70710678118654752f));
                    float g1 = 0.5f * v1 * (1.0f + erff(v1 * 0.70710678118654752f));
                    __nv_bfloat16 h0 = __float2bfloat16(g0);
                    __nv_bfloat16 h1 = __float2bfloat16(g1);
                    __nv_bfloat16 l0 = __float2bfloat16(g0 - __bfloat162float(h0));
                    __nv_bfloat16 l1 = __float2bfloat16(g1 - __bfloat162float(h1));
                    *(__nv_bfloat162*)(g_hhi + (size_t)p * 48 + c) = __nv_bfloat162(h0, h1);
                    *(__nv_bfloat162*)(g_hlo + (size_t)p * 48 + c) = __nv_bfloat162(l0, l1);
                } else {
                    *(float2*)(out + (size_t)p * COUT + c) = make_float2(v0, v1);
                }
            }
        }
    }
}

// ---------------- launch ----------------
extern "C" void kernel_launch(void* const* d_in, const int* in_sizes, int n_in,
                              void* d_out, int out_size) {
    const float* features = (const float*)d_in[0];   // [400000, 64]  f32
    const int*   nbr      = (const int*)d_in[1];     // [27, 400000]  i32
    const float* W1       = (const float*)d_in[2];   // [27, 64, 38]  f32
    const float* W2       = (const float*)d_in[3];   // [27, 38, 38]  f32
    float* out = (float*)d_out;                      // [400000, 38]  f32

    __nv_bfloat16 *fhi, *flo, *hhi, *hlo, *w1h, *w1l, *w2h, *w2l;
    cudaGetSymbolAddress((void**)&fhi, g_fhi);
    cudaGetSymbolAddress((void**)&flo, g_flo);
    cudaGetSymbolAddress((void**)&hhi, g_hhi);
    cudaGetSymbolAddress((void**)&hlo, g_hlo);
    cudaGetSymbolAddress((void**)&w1h, g_w1hi);
    cudaGetSymbolAddress((void**)&w1l, g_w1lo);
    cudaGetSymbolAddress((void**)&w2h, g_w2hi);
    cudaGetSymbolAddress((void**)&w2l, g_w2lo);

    long nf = (long)NP * 64;
    k_prep_f <<<(unsigned)((nf + 255) / 256), 256>>>(features, nf);
    k_prep_w1<<<(NKER * CIN  * COUT + 255) / 256, 256>>>(W1);
    k_prep_w2<<<(NKER * COUT * COUT + 255) / 256, 256>>>(W2);

    layer_kernel<8, 4, true ><<<NTILE, 128, SMEM_DYN>>>(fhi, flo, w1h, w1l, nbr, nullptr);
    layer_kernel<6, 3, false><<<NTILE, 128, SMEM_DYN>>>(hhi, hlo, w2h, w2l, nbr, out);
}

// round 17
// speedup vs baseline: 36.0392x; 1.0172x over previous
#include <cuda_runtime.h>
#include <cuda_bf16.h>
#include <cstdint>
#include <math.h>

#define NP    400000
#define NKER  27
#define CIN   64
#define COUT  38
#define NTILE 3125              // 3125*128 == 400000 exactly

// smem: A rows (128) + W rows (40), all padded to 144B row stride
#define ROWPAD   144
#define A_PLANE  (128 * ROWPAD)          // 18432
#define SM_W     (2 * A_PLANE)           // 36864
#define W_PLANE  (40 * ROWPAD)           // 5760
#define SMEM_DYN (SM_W + 2 * W_PLANE)    // 48384  (<= 48KB default, 4 CTA/SM)

// ---- device-global scratch (zero-initialized at module load; padding row NP
//      and pad columns are NEVER written, so they stay zero) ----
__device__ __align__(256) __nv_bfloat16 g_fhi[(NP + 1) * 64];
__device__ __align__(256) __nv_bfloat16 g_flo[(NP + 1) * 64];
__device__ __align__(256) __nv_bfloat16 g_hhi[(NP + 1) * 48];   // cols 38..47 stay 0
__device__ __align__(256) __nv_bfloat16 g_hlo[(NP + 1) * 48];
__device__ __align__(256) __nv_bfloat16 g_w1hi[NKER * 40 * 64]; // [k][cout(40)][cin]
__device__ __align__(256) __nv_bfloat16 g_w1lo[NKER * 40 * 64];
__device__ __align__(256) __nv_bfloat16 g_w2hi[NKER * 40 * 48];
__device__ __align__(256) __nv_bfloat16 g_w2lo[NKER * 40 * 48];

// ---------------- helpers ----------------
__device__ __forceinline__ uint32_t smem_u32(const void* p) {
    uint32_t a;
    asm("{ .reg .u64 t; cvta.to.shared.u64 t, %1; cvt.u32.u64 %0, t; }" : "=r"(a) : "l"(p));
    return a;
}
__device__ __forceinline__ void ldsm_x4(uint32_t* r, uint32_t addr) {
    asm volatile("ldmatrix.sync.aligned.m8n8.x4.shared.b16 {%0,%1,%2,%3}, [%4];"
                 : "=r"(r[0]), "=r"(r[1]), "=r"(r[2]), "=r"(r[3]) : "r"(addr));
}
__device__ __forceinline__ void mma_bf16(float* d, const uint32_t* a, const uint32_t* b) {
    asm volatile(
        "mma.sync.aligned.m16n8k16.row.col.f32.bf16.bf16.f32 "
        "{%0,%1,%2,%3}, {%4,%5,%6,%7}, {%8,%9}, {%0,%1,%2,%3};"
        : "+f"(d[0]), "+f"(d[1]), "+f"(d[2]), "+f"(d[3])
        : "r"(a[0]), "r"(a[1]), "r"(a[2]), "r"(a[3]), "r"(b[0]), "r"(b[1]));
}

// ---------------- prep kernels ----------------
__global__ void k_prep_f(const float* __restrict__ f, long n) {
    long i = (long)blockIdx.x * blockDim.x + threadIdx.x;
    if (i >= n) return;
    float x = f[i];
    __nv_bfloat16 h = __float2bfloat16(x);
    __nv_bfloat16 l = __float2bfloat16(x - __bfloat162float(h));
    g_fhi[i] = h; g_flo[i] = l;
}
__global__ void k_prep_w1(const float* __restrict__ w) {
    int t = blockIdx.x * blockDim.x + threadIdx.x;
    if (t >= NKER * CIN * COUT) return;
    int k  = t / (CIN * COUT);
    int r  = t - k * CIN * COUT;
    int ci = r / COUT;
    int co = r - ci * COUT;
    float x = w[t];
    __nv_bfloat16 h = __float2bfloat16(x);
    __nv_bfloat16 l = __float2bfloat16(x - __bfloat162float(h));
    int di = (k * 40 + co) * 64 + ci;
    g_w1hi[di] = h; g_w1lo[di] = l;
}
__global__ void k_prep_w2(const float* __restrict__ w) {
    int t = blockIdx.x * blockDim.x + threadIdx.x;
    if (t >= NKER * COUT * COUT) return;
    int k  = t / (COUT * COUT);
    int r  = t - k * COUT * COUT;
    int ci = r / COUT;
    int co = r - ci * COUT;
    float x = w[t];
    __nv_bfloat16 h = __float2bfloat16(x);
    __nv_bfloat16 l = __float2bfloat16(x - __bfloat162float(h));
    int di = (k * 40 + co) * 48 + ci;
    g_w2hi[di] = h; g_w2lo[di] = l;
}

// ---------------- main layer kernel ----------------
// out[i] = sum_k W[k]^T A[nbr[k,i]] via HMMA, bf16 2-term split (3 mma passes).
// ROWB16: 16B chunks per feature row (8 -> 64 cols, 6 -> 48 cols); KSTEPS = k16 chunks.
template<int ROWB16, int KSTEPS, bool IS_L1>
__global__ void __launch_bounds__(128)
layer_kernel(const __nv_bfloat16* __restrict__ Ahi, const __nv_bfloat16* __restrict__ Alo,
             const __nv_bfloat16* __restrict__ Whi, const __nv_bfloat16* __restrict__ Wlo,
             const int* __restrict__ nbr, float* __restrict__ out) {
    extern __shared__ char smem[];
    const uint32_t sbase = smem_u32(smem);
    const int t    = threadIdx.x;
    const int wid  = t >> 5, lane = t & 31;
    const int tile = blockIdx.x;
    const int ROWE = ROWB16 * 8;   // bf16 elems per row in global planes

    float acc[2][5][4];
    #pragma unroll
    for (int m = 0; m < 2; m++)
        #pragma unroll
        for (int n = 0; n < 5; n++)
            #pragma unroll
            for (int j = 0; j < 4; j++) acc[m][n][j] = 0.0f;

    const uint32_t smA_hi = sbase;
    const uint32_t smA_lo = sbase + A_PLANE;
    const uint32_t smW_hi = sbase + SM_W;
    const uint32_t smW_lo = smW_hi + W_PLANE;

    // B ldmatrix.x4 lane base: m0=hi k0-7, m1=hi k8-15, m2=lo k0-7, m3=lo k8-15
    const uint32_t bbase = ((lane & 16) ? smW_lo : smW_hi)
                         + (uint32_t)(lane & 7) * ROWPAD + ((lane >> 3) & 1) * 16;
    // A ldmatrix.x4 lane pieces
    const uint32_t arow  = (uint32_t)(wid * 32 + (lane & 15)) * ROWPAD;
    const uint32_t ahalf = (uint32_t)((lane >> 4) * 16);

    // coalesced-gather lane mapping: 4 rows x 8 chunks per warp instruction
    const int gg = lane >> 3;                 // row group 0..3
    const int cc = lane & 7;                  // 16B chunk 0..7
    const bool cok = (cc < ROWB16);

    for (int k = 0; k < NKER; k++) {
        // each thread reads the neighbor index for ITS row (coalesced int load)
        const int idx_own = nbr[(size_t)k * NP + tile * 128 + t];
        __syncthreads();   // previous compute done before overwriting smem
        // ---- coalesced cooperative gather: warp covers its 32 rows, 4/iter ----
        #pragma unroll
        for (int it = 0; it < 8; it++) {
            const int rl  = it * 4 + gg;                          // row within warp
            const int idx = __shfl_sync(0xffffffffu, idx_own, rl); // NP -> zero row
            if (cok) {
                const uint4 vh = *((const uint4*)(Ahi + (size_t)idx * ROWE) + cc);
                const uint4 vl = *((const uint4*)(Alo + (size_t)idx * ROWE) + cc);
                const uint32_t d = (uint32_t)(wid * 32 + rl) * ROWPAD + cc * 16;
                *(uint4*)(smem + d)           = vh;
                *(uint4*)(smem + A_PLANE + d) = vl;
            }
        }
        // ---- stage W[k] tile: 40 rows x ROWB16 chunks, hi + lo ----
        {
            const uint4* wh = (const uint4*)(Whi + (size_t)k * 40 * ROWE);
            const uint4* wl = (const uint4*)(Wlo + (size_t)k * 40 * ROWE);
            for (int i = t; i < 40 * ROWB16; i += 128) {
                int n = i / ROWB16, j = i - n * ROWB16;
                ((uint4*)(smem + SM_W + (size_t)n * ROWPAD))[j] = wh[i];
                ((uint4*)(smem + SM_W + W_PLANE + (size_t)n * ROWPAD))[j] = wl[i];
            }
        }
        __syncthreads();
        // ---- compute ----
        #pragma unroll
        for (int s = 0; s < KSTEPS; s++) {
            uint32_t bh[5][2], bl[5][2];
            #pragma unroll
            for (int nt = 0; nt < 5; nt++) {
                uint32_t r[4];
                ldsm_x4(r, bbase + (uint32_t)(nt * 8) * ROWPAD + s * 32);
                bh[nt][0] = r[0]; bh[nt][1] = r[1];
                bl[nt][0] = r[2]; bl[nt][1] = r[3];
            }
            #pragma unroll
            for (int mt = 0; mt < 2; mt++) {
                uint32_t ah[4], al[4];
                const uint32_t ao = arow + (uint32_t)(mt * 16) * ROWPAD + s * 32 + ahalf;
                ldsm_x4(ah, smA_hi + ao);
                ldsm_x4(al, smA_lo + ao);
                #pragma unroll
                for (int nt = 0; nt < 5; nt++) {
                    mma_bf16(acc[mt][nt], ah, bh[nt]);   // hi*hi
                    mma_bf16(acc[mt][nt], ah, bl[nt]);   // hi*lo
                    mma_bf16(acc[mt][nt], al, bh[nt]);   // lo*hi
                }
            }
        }
    }

    // ---- epilogue ----
    const int rbase = wid * 32 + (lane >> 2);
    #pragma unroll
    for (int mt = 0; mt < 2; mt++) {
        const int p0 = tile * 128 + rbase + mt * 16;     // rows p0, p0+8
        #pragma unroll
        for (int nt = 0; nt < 5; nt++) {
            const int c = nt * 8 + (lane & 3) * 2;
            if (c >= COUT) continue;                     // cols 38,39 discarded
            #pragma unroll
            for (int h = 0; h < 2; h++) {
                const int p = p0 + h * 8;
                float v0 = acc[mt][nt][2 * h + 0];
                float v1 = acc[mt][nt][2 * h + 1];
                if (IS_L1) {
                    float g0 = 0.5f * v0 * (1.0f + erff(v0 * 0.70710678118654752f));
                    float g1 = 0.5f * v1 * (1.0f + erff(v1 * 0.70710678118654752f));
                    __nv_bfloat16 h0 = __float2bfloat16(g0);
                    __nv_bfloat16 h1 = __float2bfloat16(g1);
                    __nv_bfloat16 l0 = __float2bfloat16(g0 - __bfloat162float(h0));
                    __nv_bfloat16 l1 = __float2bfloat16(g1 - __bfloat162float(h1));
                    *(__nv_bfloat162*)(g_hhi + (size_t)p * 48 + c) = __nv_bfloat162(h0, h1);
                    *(__nv_bfloat162*)(g_hlo + (size_t)p * 48 + c) = __nv_bfloat162(l0, l1);
                } else {
                    *(float2*)(out + (size_t)p * COUT + c) = make_float2(v0, v1);
                }
            }
        }
    }
}

// ---------------- launch ----------------
extern "C" void kernel_launch(void* const* d_in, const int* in_sizes, int n_in,
                              void* d_out, int out_size) {
    const float* features = (const float*)d_in[0];   // [400000, 64]  f32
    const int*   nbr      = (const int*)d_in[1];     // [27, 400000]  i32
    const float* W1       = (const float*)d_in[2];   // [27, 64, 38]  f32
    const float* W2       = (const float*)d_in[3];   // [27, 38, 38]  f32
    float* out = (float*)d_out;                      // [400000, 38]  f32

    __nv_bfloat16 *fhi, *flo, *hhi, *hlo, *w1h, *w1l, *w2h, *w2l;
    cudaGetSymbolAddress((void**)&fhi, g_fhi);
    cudaGetSymbolAddress((void**)&flo, g_flo);
    cudaGetSymbolAddress((void**)&hhi, g_hhi);
    cudaGetSymbolAddress((void**)&hlo, g_hlo);
    cudaGetSymbolAddress((void**)&w1h, g_w1hi);
    cudaGetSymbolAddress((void**)&w1l, g_w1lo);
    cudaGetSymbolAddress((void**)&w2h, g_w2hi);
    cudaGetSymbolAddress((void**)&w2l, g_w2lo);

    long nf = (long)NP * 64;
    k_prep_f <<<(unsigned)((nf + 255) / 256), 256>>>(features, nf);
    k_prep_w1<<<(NKER * CIN  * COUT + 255) / 256, 256>>>(W1);
    k_prep_w2<<<(NKER * COUT * COUT + 255) / 256, 256>>>(W2);

    layer_kernel<8, 4, true ><<<NTILE, 128, SMEM_DYN>>>(fhi, flo, w1h, w1l, nbr, nullptr);
    layer_kernel<6, 3, false><<<NTILE, 128, SMEM_DYN>>>(hhi, hlo, w2h, w2l, nbr, out);
}